// round 7
// baseline (speedup 1.0000x reference)
#include <cuda_runtime.h>

// QnnFormerVQC round 7: single kernel. Each block (128 threads):
//  1) all threads load 2 batch elements, compute encoding tensor p (real);
//  2) threads build shared param tables; threads 0-15 evolve the 16 basis
//     states through the verified reduced circuit -> Wsh[16][16] (the fixed
//     16x16 complex unitary for all 3 layers, RX(beta0/1) folded into U,
//     RX(beta2) folded into measurement);
//  3) psi = W @ p per element (complex x real matvec, LDS.128 broadcast rows
//     shared across the thread's TWO elements), then measurement epilogue.
// Bit convention: qubit q <-> mask (8 >> q), qubit 0 = MSB.

#define NQ 4
#define NL 3

struct PS {
    float2 U[NL][NQ][2][2];
    float  ce[NL][NQ], se[NL][NQ];
    float2 dg[NL][16];
};

__device__ __forceinline__ float2 cmulh(float2 a, float2 b) {
    return make_float2(a.x * b.x - a.y * b.y, a.x * b.y + a.y * b.x);
}
__device__ __forceinline__ float2 caddh(float2 a, float2 b) {
    return make_float2(a.x + b.x, a.y + b.y);
}

// measurement with RX(beta2) folded in; writes res[12]
__device__ __forceinline__ void measure(const float2* psi, float cb, float sb,
                                        float* res) {
    // shared |psi_i|^2 for Z
    float sq[16];
    #pragma unroll
    for (int i = 0; i < 16; i++)
        sq[i] = fmaf(psi[i].x, psi[i].x, psi[i].y * psi[i].y);
    float T = 0.f;
    #pragma unroll
    for (int i = 0; i < 16; i++) T += sq[i];

    #pragma unroll
    for (int q = 0; q < NQ; q++) {
        int mask = 8 >> q;
        float s1 = 0.f;
        #pragma unroll
        for (int i = 0; i < 16; i++)
            if (i & mask) s1 += sq[i];
        float z = fmaf(-2.f, s1, T);

        float xr = 0.f, yi = 0.f;
        #pragma unroll
        for (int i = 0; i < 16; i++) {
            if (i & mask) continue;
            int j = i | mask;
            float2 a = psi[i], d = psi[j];
            xr = fmaf(a.x, d.x, xr); xr = fmaf(a.y, d.y, xr);   // Re(conj(a)d)
            yi = fmaf(a.x, d.y, yi); yi = fmaf(-a.y, d.x, yi);  // Im(conj(a)d)
        }
        float xo = 2.f * xr, yo = 2.f * yi;
        res[q]     = fmaf(cb, z, sb * yo);      // z' = cb*z + sb*y
        res[4 + q] = xo;                        // x' = x
        res[8 + q] = fmaf(cb, yo, -sb * z);     // y' = cb*y - sb*z
    }
}

__global__ void __launch_bounds__(128) vqc_kernel(const float4* __restrict__ x,
                                                  float* __restrict__ out,
                                                  const float* __restrict__ w,
                                                  const float* __restrict__ ew,
                                                  const float* __restrict__ gam,
                                                  const float* __restrict__ bet,
                                                  int n2) {
    __shared__ PS ps;
    __shared__ float2 Wsh[16][16];
    __shared__ float2 mbsh;
    int t = threadIdx.x;
    int b = blockIdx.x * blockDim.x + t;
    bool act = (b < n2);

    // ---- 1) per-thread encoding (independent of shared state) ----
    float p0[16], p1[16];
    if (act) {
        float4 x0 = x[2 * b];
        float4 x1 = x[2 * b + 1];
        float c0[4], s0[4], c1[4], s1[4];
        __sincosf(0.5f * x0.x, &s0[0], &c0[0]);
        __sincosf(0.5f * x0.y, &s0[1], &c0[1]);
        __sincosf(0.5f * x0.z, &s0[2], &c0[2]);
        __sincosf(0.5f * x0.w, &s0[3], &c0[3]);
        __sincosf(0.5f * x1.x, &s1[0], &c1[0]);
        __sincosf(0.5f * x1.y, &s1[1], &c1[1]);
        __sincosf(0.5f * x1.z, &s1[2], &c1[2]);
        __sincosf(0.5f * x1.w, &s1[3], &c1[3]);
        float a01[4], a012[8];
        a01[0] = c0[0] * c0[1]; a01[1] = c0[0] * s0[1];
        a01[2] = s0[0] * c0[1]; a01[3] = s0[0] * s0[1];
        #pragma unroll
        for (int k = 0; k < 4; k++) {
            a012[2 * k]     = a01[k] * c0[2];
            a012[2 * k + 1] = a01[k] * s0[2];
        }
        #pragma unroll
        for (int m = 0; m < 8; m++) {
            p0[2 * m]     = a012[m] * c0[3];
            p0[2 * m + 1] = a012[m] * s0[3];
        }
        a01[0] = c1[0] * c1[1]; a01[1] = c1[0] * s1[1];
        a01[2] = s1[0] * c1[1]; a01[3] = s1[0] * s1[1];
        #pragma unroll
        for (int k = 0; k < 4; k++) {
            a012[2 * k]     = a01[k] * c1[2];
            a012[2 * k + 1] = a01[k] * s1[2];
        }
        #pragma unroll
        for (int m = 0; m < 8; m++) {
            p1[2 * m]     = a012[m] * c1[3];
            p1[2 * m + 1] = a012[m] * s1[3];
        }
    }

    // ---- 2) per-block parameter tables ----
    if (t < NL * NQ) {
        int L = t / NQ, q = t % NQ;
        float th = w[L * NQ + q];
        float c, s;
        sincosf(0.5f * th, &s, &c);
        float2 RX[2][2] = {{{c, 0.f}, {0.f, -s}}, {{0.f, -s}, {c, 0.f}}};
        float2 RY[2][2] = {{{c, 0.f}, {-s, 0.f}}, {{s, 0.f}, {c, 0.f}}};
        float2 RZ[2][2] = {{{c, -s}, {0.f, 0.f}}, {{0.f, 0.f}, {c, s}}};
        float2 T[2][2], M[2][2];
        #pragma unroll
        for (int i = 0; i < 2; i++)
            #pragma unroll
            for (int j = 0; j < 2; j++)
                T[i][j] = caddh(cmulh(RY[i][0], RX[0][j]), cmulh(RY[i][1], RX[1][j]));
        #pragma unroll
        for (int i = 0; i < 2; i++)
            #pragma unroll
            for (int j = 0; j < 2; j++)
                M[i][j] = caddh(cmulh(RZ[i][0], T[0][j]), cmulh(RZ[i][1], T[1][j]));
        if (L > 0) {  // fold previous layer's RX(beta): M_eff = M * RXb
            float cb, sb;
            sincosf(0.5f * bet[L - 1], &sb, &cb);
            float2 RXb[2][2] = {{{cb, 0.f}, {0.f, -sb}}, {{0.f, -sb}, {cb, 0.f}}};
            float2 E[2][2];
            #pragma unroll
            for (int i = 0; i < 2; i++)
                #pragma unroll
                for (int j = 0; j < 2; j++)
                    E[i][j] = caddh(cmulh(M[i][0], RXb[0][j]), cmulh(M[i][1], RXb[1][j]));
            #pragma unroll
            for (int i = 0; i < 2; i++)
                #pragma unroll
                for (int j = 0; j < 2; j++)
                    M[i][j] = E[i][j];
        }
        #pragma unroll
        for (int i = 0; i < 2; i++)
            #pragma unroll
            for (int j = 0; j < 2; j++)
                ps.U[L][q][i][j] = M[i][j];
        sincosf(0.5f * ew[L * NQ + q], &ps.se[L][q], &ps.ce[L][q]);
    }
    if (t >= 16 && t < 16 + NL * 16) {
        int r = t - 16;
        int L = r / 16, idx = r % 16;
        int k = 0;
        #pragma unroll
        for (int i = 0; i < 3; i++) {
            int bi = (idx >> (3 - i)) & 1;
            int bj = (idx >> (2 - i)) & 1;
            if (bi == bj) k++;
        }
        float ang = 0.5f * gam[L] * (float)(3 - 2 * k);
        float sa, ca;
        sincosf(ang, &sa, &ca);
        ps.dg[L][idx] = make_float2(ca, sa);
    }
    if (t == 64) {
        float cb, sb;
        sincosf(bet[NL - 1], &sb, &cb);  // FULL angle
        mbsh = make_float2(cb, sb);
    }
    __syncthreads();

    // ---- basis evolution: thread t < 16 owns column t of W ----
    if (t < 16) {
        float2 psi[16];
        #pragma unroll
        for (int i = 0; i < 16; i++) psi[i] = make_float2(0.f, 0.f);
        psi[t] = make_float2(1.f, 0.f);

        #pragma unroll
        for (int L = 0; L < NL; L++) {
            #pragma unroll
            for (int q = 0; q < NQ; q++) {
                float2 u00 = ps.U[L][q][0][0], u01 = ps.U[L][q][0][1];
                float2 u10 = ps.U[L][q][1][0], u11 = ps.U[L][q][1][1];
                int mask = 8 >> q;
                #pragma unroll
                for (int i = 0; i < 16; i++) {
                    if (i & mask) continue;
                    int j = i | mask;
                    float2 a = psi[i], d = psi[j];
                    float nr, ni, mr, mi;
                    nr = u00.x * a.x; nr = fmaf(-u00.y, a.y, nr);
                    nr = fmaf(u01.x, d.x, nr); nr = fmaf(-u01.y, d.y, nr);
                    ni = u00.x * a.y; ni = fmaf(u00.y, a.x, ni);
                    ni = fmaf(u01.x, d.y, ni); ni = fmaf(u01.y, d.x, ni);
                    mr = u10.x * a.x; mr = fmaf(-u10.y, a.y, mr);
                    mr = fmaf(u11.x, d.x, mr); mr = fmaf(-u11.y, d.y, mr);
                    mi = u10.x * a.y; mi = fmaf(u10.y, a.x, mi);
                    mi = fmaf(u11.x, d.y, mi); mi = fmaf(u11.y, d.x, mi);
                    psi[i] = make_float2(nr, ni);
                    psi[j] = make_float2(mr, mi);
                }
            }
            #pragma unroll
            for (int q = 0; q < NQ; q++) {
                float c = ps.ce[L][q], s = ps.se[L][q];
                int cmask = 8 >> q;
                int tmask = 8 >> ((q + 1) & 3);
                #pragma unroll
                for (int i = 0; i < 16; i++) {
                    if (!(i & cmask) || (i & tmask)) continue;
                    int j = i | tmask;
                    float2 a = psi[i], d = psi[j];
                    psi[i] = make_float2(fmaf(c, a.x,  s * d.y),
                                         fmaf(c, a.y, -s * d.x));
                    psi[j] = make_float2(fmaf(s, a.y,  c * d.x),
                                         fmaf(-s, a.x, c * d.y));
                }
            }
            {   // diffuser
                float sr = (psi[9].x + psi[11].x) + (psi[13].x + psi[15].x);
                float si = (psi[9].y + psi[11].y) + (psi[13].y + psi[15].y);
                sr *= 0.5f; si *= 0.5f;
                psi[9].x  -= sr; psi[9].y  -= si;
                psi[11].x -= sr; psi[11].y -= si;
                psi[13].x -= sr; psi[13].y -= si;
                psi[15].x -= sr; psi[15].y -= si;
            }
            #pragma unroll
            for (int i = 0; i < 16; i++) {  // RZZ diagonal
                float2 ph = ps.dg[L][i];
                float2 a = psi[i];
                psi[i] = make_float2(fmaf(ph.x, a.x, -ph.y * a.y),
                                     fmaf(ph.x, a.y,  ph.y * a.x));
            }
        }
        #pragma unroll
        for (int i = 0; i < 16; i++) Wsh[i][t] = psi[i];
    }
    __syncthreads();

    if (!act) return;

    // ---- 3) psi = W @ p for both elements (LDS rows shared) ----
    float2 psi0[16], psi1[16];
    #pragma unroll
    for (int i = 0; i < 16; i++) {
        const float4* row = reinterpret_cast<const float4*>(&Wsh[i][0]);
        float re0 = 0.f, im0 = 0.f, re1 = 0.f, im1 = 0.f;
        #pragma unroll
        for (int jj = 0; jj < 8; jj++) {
            float4 v = row[jj];  // (W[i][2jj].re,.im, W[i][2jj+1].re,.im)
            re0 = fmaf(v.x, p0[2 * jj], re0);
            im0 = fmaf(v.y, p0[2 * jj], im0);
            re0 = fmaf(v.z, p0[2 * jj + 1], re0);
            im0 = fmaf(v.w, p0[2 * jj + 1], im0);
            re1 = fmaf(v.x, p1[2 * jj], re1);
            im1 = fmaf(v.y, p1[2 * jj], im1);
            re1 = fmaf(v.z, p1[2 * jj + 1], re1);
            im1 = fmaf(v.w, p1[2 * jj + 1], im1);
        }
        psi0[i] = make_float2(re0, im0);
        psi1[i] = make_float2(re1, im1);
    }

    float cb = mbsh.x, sb = mbsh.y;
    float res0[12], res1[12];
    measure(psi0, cb, sb, res0);
    measure(psi1, cb, sb, res1);

    float4* o0 = reinterpret_cast<float4*>(out + (size_t)(2 * b) * 12);
    o0[0] = make_float4(res0[0], res0[1], res0[2],  res0[3]);
    o0[1] = make_float4(res0[4], res0[5], res0[6],  res0[7]);
    o0[2] = make_float4(res0[8], res0[9], res0[10], res0[11]);
    float4* o1 = reinterpret_cast<float4*>(out + (size_t)(2 * b + 1) * 12);
    o1[0] = make_float4(res1[0], res1[1], res1[2],  res1[3]);
    o1[1] = make_float4(res1[4], res1[5], res1[6],  res1[7]);
    o1[2] = make_float4(res1[8], res1[9], res1[10], res1[11]);
}

extern "C" void kernel_launch(void* const* d_in, const int* in_sizes, int n_in,
                              void* d_out, int out_size) {
    const float* x   = (const float*)d_in[0];  // (B, 4)
    const float* w   = (const float*)d_in[1];  // (3, 4)
    const float* ew  = (const float*)d_in[2];  // (3, 4)
    const float* gam = (const float*)d_in[3];  // (3,)
    const float* bet = (const float*)d_in[4];  // (3,)
    float* out = (float*)d_out;                // (B, 12)

    int n = in_sizes[0] / 4;
    int n2 = n / 2;  // two elements per thread (B is even)

    int threads = 128;
    int blocks = (n2 + threads - 1) / threads;
    vqc_kernel<<<blocks, threads>>>((const float4*)x, out, w, ew, gam, bet, n2);
}

// round 8
// speedup vs baseline: 1.1099x; 1.1099x over previous
#include <cuda_runtime.h>

// QnnFormerVQC round 8: round-6 two-kernel structure (tiny prep kernel builds
// the fixed 16x16 circuit unitary W; main kernel does psi = W @ p per element)
// + PDL (programmatic dependent launch): the main kernel launches while prep
// is still in flight, does all W-independent work (x load, sincos, encoding
// tensor p), THEN cudaGridDependencySynchronize() before reading W.
//
// Verified reductions (oracle: round-3 literal kernel):
//  - whole 3-layer shared-parameter circuit == one 16x16 complex unitary W
//    (RX(beta0/1) folded into next layer's U; reference's _apmcx = swap 7<->15)
//  - p = tensor_q (cos x_q/2, sin x_q/2) is REAL -> matvec is 512 FMA
//  - RX(beta2) folded into measurement: z'=cb*z+sb*y, y'=cb*y-sb*z, x'=x
// Bit convention: qubit q <-> mask (8 >> q), qubit 0 = MSB.

#define NQ 4
#define NL 3

__device__ float2 g_W[16][16];   // W[i][j] = <i| circuit |j>
__device__ float2 g_mb;          // (cos(beta2), sin(beta2)), FULL angle

__device__ __forceinline__ float2 cmulh(float2 a, float2 b) {
    return make_float2(a.x * b.x - a.y * b.y, a.x * b.y + a.y * b.x);
}
__device__ __forceinline__ float2 caddh(float2 a, float2 b) {
    return make_float2(a.x + b.x, a.y + b.y);
}

struct PS {
    float2 U[NL][NQ][2][2];
    float  ce[NL][NQ], se[NL][NQ];
    float2 dg[NL][16];
};

__global__ void prep_kernel(const float* __restrict__ w,
                            const float* __restrict__ ew,
                            const float* __restrict__ gam,
                            const float* __restrict__ bet) {
    __shared__ PS ps;
    int t = threadIdx.x;

    if (t < NL * NQ) {
        int L = t / NQ, q = t % NQ;
        float th = w[L * NQ + q];
        float c, s;
        sincosf(0.5f * th, &s, &c);
        float2 RX[2][2] = {{{c, 0.f}, {0.f, -s}}, {{0.f, -s}, {c, 0.f}}};
        float2 RY[2][2] = {{{c, 0.f}, {-s, 0.f}}, {{s, 0.f}, {c, 0.f}}};
        float2 RZ[2][2] = {{{c, -s}, {0.f, 0.f}}, {{0.f, 0.f}, {c, s}}};
        float2 T[2][2], M[2][2];
        #pragma unroll
        for (int i = 0; i < 2; i++)
            #pragma unroll
            for (int j = 0; j < 2; j++)
                T[i][j] = caddh(cmulh(RY[i][0], RX[0][j]), cmulh(RY[i][1], RX[1][j]));
        #pragma unroll
        for (int i = 0; i < 2; i++)
            #pragma unroll
            for (int j = 0; j < 2; j++)
                M[i][j] = caddh(cmulh(RZ[i][0], T[0][j]), cmulh(RZ[i][1], T[1][j]));
        if (L > 0) {  // fold previous layer's RX(beta): M_eff = M * RXb
            float cb, sb;
            sincosf(0.5f * bet[L - 1], &sb, &cb);
            float2 RXb[2][2] = {{{cb, 0.f}, {0.f, -sb}}, {{0.f, -sb}, {cb, 0.f}}};
            float2 E[2][2];
            #pragma unroll
            for (int i = 0; i < 2; i++)
                #pragma unroll
                for (int j = 0; j < 2; j++)
                    E[i][j] = caddh(cmulh(M[i][0], RXb[0][j]), cmulh(M[i][1], RXb[1][j]));
            #pragma unroll
            for (int i = 0; i < 2; i++)
                #pragma unroll
                for (int j = 0; j < 2; j++)
                    M[i][j] = E[i][j];
        }
        #pragma unroll
        for (int i = 0; i < 2; i++)
            #pragma unroll
            for (int j = 0; j < 2; j++)
                ps.U[L][q][i][j] = M[i][j];
        sincosf(0.5f * ew[L * NQ + q], &ps.se[L][q], &ps.ce[L][q]);
    }
    if (t >= 16 && t < 16 + NL * 16) {
        int r = t - 16;
        int L = r / 16, idx = r % 16;
        int k = 0;
        #pragma unroll
        for (int i = 0; i < 3; i++) {
            int bi = (idx >> (3 - i)) & 1;
            int bj = (idx >> (2 - i)) & 1;
            if (bi == bj) k++;
        }
        float ang = 0.5f * gam[L] * (float)(3 - 2 * k);
        float sa, ca;
        sincosf(ang, &sa, &ca);
        ps.dg[L][idx] = make_float2(ca, sa);
    }
    if (t == 64) {
        float cb, sb;
        sincosf(bet[NL - 1], &sb, &cb);  // FULL angle
        g_mb = make_float2(cb, sb);
    }
    __syncthreads();

    // thread t < 16 evolves basis state |t> -> column t of W
    if (t < 16) {
        float2 psi[16];
        #pragma unroll
        for (int i = 0; i < 16; i++) psi[i] = make_float2(0.f, 0.f);
        psi[t] = make_float2(1.f, 0.f);

        #pragma unroll
        for (int L = 0; L < NL; L++) {
            #pragma unroll
            for (int q = 0; q < NQ; q++) {
                float2 u00 = ps.U[L][q][0][0], u01 = ps.U[L][q][0][1];
                float2 u10 = ps.U[L][q][1][0], u11 = ps.U[L][q][1][1];
                int mask = 8 >> q;
                #pragma unroll
                for (int i = 0; i < 16; i++) {
                    if (i & mask) continue;
                    int j = i | mask;
                    float2 a = psi[i], d = psi[j];
                    float nr, ni, mr, mi;
                    nr = u00.x * a.x; nr = fmaf(-u00.y, a.y, nr);
                    nr = fmaf(u01.x, d.x, nr); nr = fmaf(-u01.y, d.y, nr);
                    ni = u00.x * a.y; ni = fmaf(u00.y, a.x, ni);
                    ni = fmaf(u01.x, d.y, ni); ni = fmaf(u01.y, d.x, ni);
                    mr = u10.x * a.x; mr = fmaf(-u10.y, a.y, mr);
                    mr = fmaf(u11.x, d.x, mr); mr = fmaf(-u11.y, d.y, mr);
                    mi = u10.x * a.y; mi = fmaf(u10.y, a.x, mi);
                    mi = fmaf(u11.x, d.y, mi); mi = fmaf(u11.y, d.x, mi);
                    psi[i] = make_float2(nr, ni);
                    psi[j] = make_float2(mr, mi);
                }
            }
            #pragma unroll
            for (int q = 0; q < NQ; q++) {
                float c = ps.ce[L][q], s = ps.se[L][q];
                int cmask = 8 >> q;
                int tmask = 8 >> ((q + 1) & 3);
                #pragma unroll
                for (int i = 0; i < 16; i++) {
                    if (!(i & cmask) || (i & tmask)) continue;
                    int j = i | tmask;
                    float2 a = psi[i], d = psi[j];
                    psi[i] = make_float2(fmaf(c, a.x,  s * d.y),
                                         fmaf(c, a.y, -s * d.x));
                    psi[j] = make_float2(fmaf(s, a.y,  c * d.x),
                                         fmaf(-s, a.x, c * d.y));
                }
            }
            {   // diffuser: psi_i -= (psi9+psi11+psi13+psi15)/2
                float sr = (psi[9].x + psi[11].x) + (psi[13].x + psi[15].x);
                float si = (psi[9].y + psi[11].y) + (psi[13].y + psi[15].y);
                sr *= 0.5f; si *= 0.5f;
                psi[9].x  -= sr; psi[9].y  -= si;
                psi[11].x -= sr; psi[11].y -= si;
                psi[13].x -= sr; psi[13].y -= si;
                psi[15].x -= sr; psi[15].y -= si;
            }
            #pragma unroll
            for (int i = 0; i < 16; i++) {  // RZZ diagonal
                float2 ph = ps.dg[L][i];
                float2 a = psi[i];
                psi[i] = make_float2(fmaf(ph.x, a.x, -ph.y * a.y),
                                     fmaf(ph.x, a.y,  ph.y * a.x));
            }
        }
        #pragma unroll
        for (int i = 0; i < 16; i++) g_W[i][t] = psi[i];
    }
}

__global__ void __launch_bounds__(256) vqc_kernel(const float4* __restrict__ x,
                                                  float* __restrict__ out,
                                                  int n) {
    __shared__ float2 Wsh[16][16];
    __shared__ float2 mbsh;
    int t = threadIdx.x;
    int b = blockIdx.x * blockDim.x + t;
    bool act = (b < n);

    // ---- W-independent phase (overlaps with prep kernel via PDL) ----
    float p[16];
    if (act) {
        float4 xv = x[b];
        float cq[4], sq[4];
        __sincosf(0.5f * xv.x, &sq[0], &cq[0]);
        __sincosf(0.5f * xv.y, &sq[1], &cq[1]);
        __sincosf(0.5f * xv.z, &sq[2], &cq[2]);
        __sincosf(0.5f * xv.w, &sq[3], &cq[3]);
        float a01[4], a012[8];
        a01[0] = cq[0] * cq[1]; a01[1] = cq[0] * sq[1];
        a01[2] = sq[0] * cq[1]; a01[3] = sq[0] * sq[1];
        #pragma unroll
        for (int k = 0; k < 4; k++) {
            a012[2 * k]     = a01[k] * cq[2];
            a012[2 * k + 1] = a01[k] * sq[2];
        }
        #pragma unroll
        for (int m = 0; m < 8; m++) {
            p[2 * m]     = a012[m] * cq[3];
            p[2 * m + 1] = a012[m] * sq[3];
        }
    }

    // ---- wait for prep kernel's W, then pull into shared ----
    cudaGridDependencySynchronize();
    if (t < 128) {
        reinterpret_cast<float4*>(&Wsh[0][0])[t] =
            reinterpret_cast<const float4*>(&g_W[0][0])[t];
    }
    if (t == 128) mbsh = g_mb;
    __syncthreads();

    if (!act) return;

    // ---- psi = W @ p (complex x real matvec, 512 FMA) ----
    float2 psi[16];
    #pragma unroll
    for (int i = 0; i < 16; i++) {
        const float4* row = reinterpret_cast<const float4*>(&Wsh[i][0]);
        float re = 0.f, im = 0.f;
        #pragma unroll
        for (int jj = 0; jj < 8; jj++) {
            float4 v = row[jj];  // (W[i][2jj].re,.im, W[i][2jj+1].re,.im)
            re = fmaf(v.x, p[2 * jj], re);
            im = fmaf(v.y, p[2 * jj], im);
            re = fmaf(v.z, p[2 * jj + 1], re);
            im = fmaf(v.w, p[2 * jj + 1], im);
        }
        psi[i] = make_float2(re, im);
    }

    // ---- measurement with RX(beta2) fold ----
    float cb = mbsh.x, sb = mbsh.y;

    float sq2[16];
    #pragma unroll
    for (int i = 0; i < 16; i++)
        sq2[i] = fmaf(psi[i].x, psi[i].x, psi[i].y * psi[i].y);
    float T = 0.f;
    #pragma unroll
    for (int i = 0; i < 16; i++) T += sq2[i];

    float res[12];
    #pragma unroll
    for (int q = 0; q < NQ; q++) {
        int mask = 8 >> q;
        float s1 = 0.f;
        #pragma unroll
        for (int i = 0; i < 16; i++)
            if (i & mask) s1 += sq2[i];
        float z = fmaf(-2.f, s1, T);

        float xr = 0.f, yi = 0.f;
        #pragma unroll
        for (int i = 0; i < 16; i++) {
            if (i & mask) continue;
            int j = i | mask;
            float2 a = psi[i], d = psi[j];
            xr = fmaf(a.x, d.x, xr); xr = fmaf(a.y, d.y, xr);   // Re(conj(a)d)
            yi = fmaf(a.x, d.y, yi); yi = fmaf(-a.y, d.x, yi);  // Im(conj(a)d)
        }
        float xo = 2.f * xr, yo = 2.f * yi;
        res[q]     = fmaf(cb, z, sb * yo);      // z' = cb*z + sb*y
        res[4 + q] = xo;                        // x' = x
        res[8 + q] = fmaf(cb, yo, -sb * z);     // y' = cb*y - sb*z
    }

    float4* o = reinterpret_cast<float4*>(out + (size_t)b * 12);
    o[0] = make_float4(res[0], res[1], res[2],  res[3]);
    o[1] = make_float4(res[4], res[5], res[6],  res[7]);
    o[2] = make_float4(res[8], res[9], res[10], res[11]);
}

extern "C" void kernel_launch(void* const* d_in, const int* in_sizes, int n_in,
                              void* d_out, int out_size) {
    const float* x   = (const float*)d_in[0];  // (B, 4)
    const float* w   = (const float*)d_in[1];  // (3, 4)
    const float* ew  = (const float*)d_in[2];  // (3, 4)
    const float* gam = (const float*)d_in[3];  // (3,)
    const float* bet = (const float*)d_in[4];  // (3,)
    float* out = (float*)d_out;                // (B, 12)

    int n = in_sizes[0] / 4;

    prep_kernel<<<1, 128>>>(w, ew, gam, bet);

    // Main kernel with Programmatic Dependent Launch: blocks may start while
    // prep is still running; they synchronize via cudaGridDependencySynchronize
    // before touching g_W.
    int threads = 256;
    int blocks = (n + threads - 1) / threads;

    cudaLaunchConfig_t cfg = {};
    cfg.gridDim = dim3((unsigned)blocks, 1, 1);
    cfg.blockDim = dim3((unsigned)threads, 1, 1);
    cfg.dynamicSmemBytes = 0;
    cudaLaunchAttribute attr[1];
    attr[0].id = cudaLaunchAttributeProgrammaticStreamSerialization;
    attr[0].val.programmaticStreamSerializationAllowed = 1;
    cfg.attrs = attr;
    cfg.numAttrs = 1;

    cudaLaunchKernelEx(&cfg, vqc_kernel, (const float4*)x, out, n);
}